// round 10
// baseline (speedup 1.0000x reference)
#include <cuda_runtime.h>
#include <cuda_bf16.h>
#include <math.h>
#include <stdint.h>

// Problem constants
#define BB 32
#define SS 1024
#define DIN 128
#define HH 256
#define G4H 1024          // 4*H
#define MROWS 32768       // B*S

// Recurrence decomposition: 2 dirs x 8 batch-groups x 8 hidden-split CTAs
#define CL 8              // cluster size (hidden split)
#define WSTRIDE 260       // W_sh row stride (floats): 16B-aligned, conflict-free
#define HSTRIDE 260       // h_sh row stride
#define REC_GRID 152      // 19 clusters: 16 real + 3 dummy (>=148 defeats low-grid throttle)

// ---------------- scratch (static device allocations; no cudaMalloc) -------
__device__ float g_xp_f[SS * BB * G4H];   // 134 MB  [t][b][4H]
__device__ float g_xp_b[SS * BB * G4H];   // 134 MB
__device__ float g_h0[BB * SS * 512];     // 67 MB   [b][t][512]
__device__ float g_h1[BB * SS * 512];     // 67 MB
__device__ float g_ctx[BB * SS * 512];    // 67 MB

__device__ __forceinline__ uint32_t smem_u32(const void* p) {
    uint32_t a;
    asm("{ .reg .u64 t; cvta.to.shared.u64 t, %1; cvt.u32.u64 %0, t; }"
        : "=r"(a) : "l"(p));
    return a;
}

// packed f32x2 FMA: acc.{lo,hi} += w.{lo,hi} * h.{lo,hi}
#define FMA2(acc, w, h) \
    asm("fma.rn.f32x2 %0, %1, %2, %0;" : "+l"(acc) : "l"(w), "l"(h))

__device__ __forceinline__ unsigned long long d2u(double d) {
    return (unsigned long long)__double_as_longlong(d);
}
__device__ __forceinline__ float f2sum(unsigned long long v) {
    float lo, hi;
    asm("mov.b64 {%0,%1}, %2;" : "=f"(lo), "=f"(hi) : "l"(v));
    return lo + hi;
}

// ---------------- tf32 tensor-core GEMM ------------------------------------
#define BK 32
#define KSTRIDE 136

__device__ __forceinline__ void mma_tf32(float* c, const uint32_t* a, const uint32_t* b) {
    asm volatile(
        "mma.sync.aligned.m16n8k8.row.col.f32.tf32.tf32.f32 "
        "{%0,%1,%2,%3}, {%4,%5,%6,%7}, {%8,%9}, {%0,%1,%2,%3};"
        : "+f"(c[0]), "+f"(c[1]), "+f"(c[2]), "+f"(c[3])
        : "r"(a[0]), "r"(a[1]), "r"(a[2]), "r"(a[3]), "r"(b[0]), "r"(b[1]));
}

__global__ void __launch_bounds__(256, 2) gemm_kernel(
    const float* __restrict__ Aext, int asel,
    const float* __restrict__ W, const float* __restrict__ bias,
    float* __restrict__ outext, int osel,
    int N, int K, long sB, long sT, int mode)
{
    const float* A = (asel == 0) ? Aext : (asel == 1 ? g_h0 : g_ctx);
    float* out = (osel == 2) ? outext : (osel == 0 ? g_xp_f : g_xp_b);

    __shared__ float As[BK][KSTRIDE];
    __shared__ float Bs[BK][KSTRIDE];

    int tid  = threadIdx.x;
    int row0 = blockIdx.x * 128;
    int col0 = blockIdx.y * 128;

    int lr = tid & 127;
    int lh = (tid >> 7) * 16;

    long aoff;
    if (mode == 0) { int R = row0 + lr; aoff = (long)(R & 31) * sB + (long)(R >> 5) * sT; }
    else           { aoff = (long)(row0 + lr) * K; }
    const float* Ap = A + aoff + lh;
    const float* Wp = W + (long)(col0 + lr) * K + lh;

    int lane = tid & 31, warp = tid >> 5;
    int wm = warp >> 1, wn = warp & 1;
    int gid = lane >> 2, tid4 = lane & 3;

    float acc[2][8][4];
#pragma unroll
    for (int mi = 0; mi < 2; mi++)
#pragma unroll
        for (int ni = 0; ni < 8; ni++)
#pragma unroll
            for (int q = 0; q < 4; q++) acc[mi][ni][q] = 0.f;

    for (int k0 = 0; k0 < K; k0 += BK) {
#pragma unroll
        for (int c = 0; c < 4; c++) {
            float4 av = *(const float4*)(Ap + k0 + c * 4);
            float4 wv = *(const float4*)(Wp + k0 + c * 4);
            int kk = lh + c * 4;
            As[kk + 0][lr] = av.x; As[kk + 1][lr] = av.y;
            As[kk + 2][lr] = av.z; As[kk + 3][lr] = av.w;
            Bs[kk + 0][lr] = wv.x; Bs[kk + 1][lr] = wv.y;
            Bs[kk + 2][lr] = wv.z; Bs[kk + 3][lr] = wv.w;
        }
        __syncthreads();

#pragma unroll
        for (int kk = 0; kk < BK; kk += 8) {
            uint32_t af[2][4];
#pragma unroll
            for (int mi = 0; mi < 2; mi++) {
                int r0 = wm * 32 + mi * 16 + gid;
                af[mi][0] = __float_as_uint(As[kk + tid4][r0]);
                af[mi][1] = __float_as_uint(As[kk + tid4][r0 + 8]);
                af[mi][2] = __float_as_uint(As[kk + tid4 + 4][r0]);
                af[mi][3] = __float_as_uint(As[kk + tid4 + 4][r0 + 8]);
            }
            uint32_t bf[8][2];
#pragma unroll
            for (int ni = 0; ni < 8; ni++) {
                int n0 = wn * 64 + ni * 8 + gid;
                bf[ni][0] = __float_as_uint(Bs[kk + tid4][n0]);
                bf[ni][1] = __float_as_uint(Bs[kk + tid4 + 4][n0]);
            }
#pragma unroll
            for (int mi = 0; mi < 2; mi++)
#pragma unroll
                for (int ni = 0; ni < 8; ni++)
                    mma_tf32(acc[mi][ni], af[mi], bf[ni]);
        }
        __syncthreads();
    }

#pragma unroll
    for (int mi = 0; mi < 2; mi++) {
        int r = row0 + wm * 32 + mi * 16 + gid;
#pragma unroll
        for (int ni = 0; ni < 8; ni++) {
            int cc = col0 + wn * 64 + ni * 8 + tid4 * 2;
            float b0 = bias[cc], b1 = bias[cc + 1];
            float2 v0 = make_float2(acc[mi][ni][0] + b0, acc[mi][ni][1] + b1);
            float2 v1 = make_float2(acc[mi][ni][2] + b0, acc[mi][ni][3] + b1);
            *(float2*)(out + (long)r * N + cc)       = v0;
            *(float2*)(out + (long)(r + 8) * N + cc) = v1;
        }
    }
}

// ---------------- recurrence: CGA clusters + f32x2 GEMV ---------------------
// 19 clusters of 8 (16 real). cluster cidx: dir = cidx>>3, bgroup = cidx&7.
// Each CTA: 32 hidden units (128 gate rows) x 4 batches.
__global__ void __launch_bounds__(256, 1) __cluster_dims__(CL, 1, 1)
rec_kernel(const float* __restrict__ w_hh_f, const float* __restrict__ w_hh_b,
           int layer)
{
    if (blockIdx.x >= 16 * CL) return;   // dummy clusters (grid padding)

    extern __shared__ float sm[];
    float* W_sh = sm;                          // [128][WSTRIDE]
    float* h_sh = sm + 128 * WSTRIDE;          // [2][4][HSTRIDE]
    float* g_sh = h_sh + 2 * 4 * HSTRIDE;      // [128][4]

    int tid = threadIdx.x;
    unsigned crank;
    asm("mov.u32 %0, %%cluster_ctarank;" : "=r"(crank));
    int cidx = blockIdx.x / CL;
    int dir  = cidx >> 3;
    int bg   = cidx & 7;

    const float* Whh = dir ? w_hh_b : w_hh_f;
    const float* xp  = dir ? g_xp_b : g_xp_f;
    float* hout = layer ? g_h1 : g_h0;

    for (int i = tid; i < 128 * 256; i += 256) {
        int r = i >> 8, k = i & 255;
        int grow = (r >> 5) * HH + (int)crank * 32 + (r & 31);
        W_sh[r * WSTRIDE + k] = Whh[(long)grow * HH + k];
    }
    for (int i = tid; i < 2 * 4 * HSTRIDE; i += 256) h_sh[i] = 0.f;
    __syncthreads();
    asm volatile("barrier.cluster.arrive.aligned;" ::: "memory");
    asm volatile("barrier.cluster.wait.aligned;"   ::: "memory");

    // GEMV mapping: warp w, lane l: rsub = l>>2, b = l&3; rows r0 = w*16+rsub, r1 = r0+8
    int lane = tid & 31, w = tid >> 5;
    int rsub = lane >> 2, b = lane & 3;
    int r0 = w * 16 + rsub, r1 = r0 + 8;
    long grow0 = (long)(r0 >> 5) * HH + crank * 32 + (r0 & 31);
    long grow1 = (long)(r1 >> 5) * HH + crank * 32 + (r1 & 31);
    int b_global = bg * 4 + b;

    // nonlin mapping (tid < 128): hidden jl = tid>>2, batch nb = tid&3
    int njl = tid >> 2, nb = tid & 3;
    float c = 0.f;

    // hoisted DSMEM peer addresses + double-buffer offsets
    uint32_t h_u32 = smem_u32(h_sh);
    uint32_t rem[CL];
#pragma unroll
    for (int pr = 0; pr < CL; pr++)
        asm("mapa.shared::cluster.u32 %0, %1, %2;" : "=r"(rem[pr]) : "r"(h_u32), "r"(pr));
    uint32_t offA = (uint32_t)(((0 * 4 + nb) * HSTRIDE + (int)crank * 32 + njl) * 4);
    uint32_t offB = (uint32_t)(((1 * 4 + nb) * HSTRIDE + (int)crank * 32 + njl) * 4);

    // xp prefetch for t=0
    int tt0 = dir ? (SS - 1) : 0;
    long xb0 = (long)tt0 * (BB * G4H) + (long)b_global * G4H;
    float xv0 = xp[xb0 + grow0];
    float xv1 = xp[xb0 + grow1];

    for (int t = 0; t < SS; t++) {
        int tt = dir ? (SS - 1 - t) : t;
        int rbuf = t & 1, wbuf = rbuf ^ 1;

        const float* w0 = W_sh + r0 * WSTRIDE;
        const float* w1 = W_sh + r1 * WSTRIDE;
        const float* hv = h_sh + (rbuf * 4 + b) * HSTRIDE;

        unsigned long long a0a = 0ull, a0b = 0ull, a1a = 0ull, a1b = 0ull;
#pragma unroll
        for (int k = 0; k < 256; k += 8) {
            double2 wa = *(const double2*)(w0 + k);
            double2 wb = *(const double2*)(w0 + k + 4);
            double2 wc = *(const double2*)(w1 + k);
            double2 wd = *(const double2*)(w1 + k + 4);
            double2 hx = *(const double2*)(hv + k);
            double2 hy = *(const double2*)(hv + k + 4);
            FMA2(a0a, d2u(wa.x), d2u(hx.x));
            FMA2(a1a, d2u(wc.x), d2u(hx.x));
            FMA2(a0a, d2u(wa.y), d2u(hx.y));
            FMA2(a1a, d2u(wc.y), d2u(hx.y));
            FMA2(a0b, d2u(wb.x), d2u(hy.x));
            FMA2(a1b, d2u(wd.x), d2u(hy.x));
            FMA2(a0b, d2u(wb.y), d2u(hy.y));
            FMA2(a1b, d2u(wd.y), d2u(hy.y));
        }
        g_sh[r0 * 4 + b] = f2sum(a0a) + f2sum(a0b) + xv0;
        g_sh[r1 * 4 + b] = f2sum(a1a) + f2sum(a1b) + xv1;
        __syncthreads();

        // prefetch xp for t+1 (flies during nonlin + push + barrier)
        if (t < SS - 1) {
            int tn = dir ? (SS - 2 - t) : (t + 1);
            long xbn = (long)tn * (BB * G4H) + (long)b_global * G4H;
            xv0 = xp[xbn + grow0];
            xv1 = xp[xbn + grow1];
        }

        if (tid < 128) {
            float gi = g_sh[(0 * 32 + njl) * 4 + nb];
            float gf = g_sh[(1 * 32 + njl) * 4 + nb];
            float gg = g_sh[(2 * 32 + njl) * 4 + nb];
            float go = g_sh[(3 * 32 + njl) * 4 + nb];
            float si = 1.f / (1.f + __expf(-gi));
            float sf = 1.f / (1.f + __expf(-gf));
            float so = 1.f / (1.f + __expf(-go));
            float tg = tanhf(gg);
            c = sf * c + si * tg;
            float hval = so * tanhf(c);

            hout[((long)(bg * 4 + nb) * SS + tt) * 512 + dir * HH + crank * 32 + njl] = hval;

            if (t < SS - 1) {
                uint32_t off = wbuf ? offB : offA;
#pragma unroll
                for (int pr = 0; pr < CL; pr++)
                    asm volatile("st.shared::cluster.f32 [%0], %1;"
                                 :: "r"(rem[pr] + off), "f"(hval) : "memory");
            }
        }

        if (t < SS - 1) {
            asm volatile("barrier.cluster.arrive.aligned;" ::: "memory");
            asm volatile("barrier.cluster.wait.aligned;"   ::: "memory");
        }
    }
}

// ---------------- attention: causal softmax-weighted running average -------
__global__ void __launch_bounds__(512) attn_kernel(
    const float* __restrict__ attn_w, const float* __restrict__ attn_b)
{
    __shared__ float aw[512];
    __shared__ float e_sh[SS];
    __shared__ float red[16];

    int b = blockIdx.x, tid = threadIdx.x;
    int lane = tid & 31, warp = tid >> 5;
    const float* hb = g_h1 + (long)b * SS * 512;

    aw[tid] = attn_w[tid];
    float sb = attn_b[0];
    __syncthreads();

    for (int t = warp; t < SS; t += 16) {
        const float* hp = hb + (long)t * 512;
        float s = 0.f;
#pragma unroll
        for (int i = lane; i < 512; i += 32) s = fmaf(hp[i], aw[i], s);
#pragma unroll
        for (int o = 16; o; o >>= 1) s += __shfl_xor_sync(0xffffffffu, s, o);
        if (lane == 0) e_sh[t] = s + sb;
    }
    __syncthreads();

    float m = -3.4e38f;
    for (int t = tid; t < SS; t += 512) m = fmaxf(m, e_sh[t]);
#pragma unroll
    for (int o = 16; o; o >>= 1) m = fmaxf(m, __shfl_xor_sync(0xffffffffu, m, o));
    if (lane == 0) red[warp] = m;
    __syncthreads();
    m = red[0];
#pragma unroll
    for (int i = 1; i < 16; i++) m = fmaxf(m, red[i]);

    for (int t = tid; t < SS; t += 512) e_sh[t] = expf(e_sh[t] - m);
    __syncthreads();

    int d = tid;
    float num = 0.f, den = 0.f;
    const float* hd = hb + d;
    float* cd = g_ctx + (long)b * SS * 512 + d;
    for (int t = 0; t < SS; t++) {
        float ev = e_sh[t];
        den += ev;
        num = fmaf(ev, hd[(long)t * 512], num);
        cd[(long)t * 512] = num / den;
    }
}

// ---------------- launch ----------------------------------------------------
extern "C" void kernel_launch(void* const* d_in, const int* in_sizes, int n_in,
                              void* d_out, int out_size)
{
    const float* x       = (const float*)d_in[0];
    const float* wih0f   = (const float*)d_in[1];
    const float* whh0f   = (const float*)d_in[2];
    const float* b0f     = (const float*)d_in[3];
    const float* wih0b   = (const float*)d_in[4];
    const float* whh0b   = (const float*)d_in[5];
    const float* b0b     = (const float*)d_in[6];
    const float* wih1f   = (const float*)d_in[7];
    const float* whh1f   = (const float*)d_in[8];
    const float* b1f     = (const float*)d_in[9];
    const float* wih1b   = (const float*)d_in[10];
    const float* whh1b   = (const float*)d_in[11];
    const float* b1b     = (const float*)d_in[12];
    const float* attn_w  = (const float*)d_in[13];
    const float* attn_b  = (const float*)d_in[14];
    const float* head_w  = (const float*)d_in[15];
    const float* head_b  = (const float*)d_in[16];
    float* out = (float*)d_out;

    const int REC_SMEM = (128 * WSTRIDE + 2 * 4 * HSTRIDE + 128 * 4) * sizeof(float);
    cudaFuncSetAttribute(rec_kernel, cudaFuncAttributeMaxDynamicSharedMemorySize, REC_SMEM);

    // ---- layer 0 ----
    gemm_kernel<<<dim3(MROWS / 128, G4H / 128), 256>>>(x, 0, wih0f, b0f, nullptr, 0,
                                                       G4H, DIN, (long)SS * DIN, DIN, 0);
    gemm_kernel<<<dim3(MROWS / 128, G4H / 128), 256>>>(x, 0, wih0b, b0b, nullptr, 1,
                                                       G4H, DIN, (long)SS * DIN, DIN, 0);
    rec_kernel<<<REC_GRID, 256, REC_SMEM>>>(whh0f, whh0b, 0);

    // ---- layer 1 ----
    gemm_kernel<<<dim3(MROWS / 128, G4H / 128), 256>>>(nullptr, 1, wih1f, b1f, nullptr, 0,
                                                       G4H, 512, (long)SS * 512, 512, 0);
    gemm_kernel<<<dim3(MROWS / 128, G4H / 128), 256>>>(nullptr, 1, wih1b, b1b, nullptr, 1,
                                                       G4H, 512, (long)SS * 512, 512, 0);
    rec_kernel<<<REC_GRID, 256, REC_SMEM>>>(whh1f, whh1b, 1);

    // ---- attention + head ----
    attn_kernel<<<BB, 512>>>(attn_w, attn_b);
    gemm_kernel<<<dim3(MROWS / 128, 1), 256>>>(nullptr, 2, head_w, head_b, out, 2,
                                               DIN, 512, 0, 0, 1);
}

// round 11
// speedup vs baseline: 1.5876x; 1.5876x over previous
#include <cuda_runtime.h>
#include <cuda_bf16.h>
#include <math.h>
#include <stdint.h>

// Problem constants
#define BB 32
#define SS 1024
#define DIN 128
#define HH 256
#define G4H 1024          // 4*H
#define MROWS 32768       // B*S

// Recurrence: 2 dirs x 8 batch-groups (clusters of 8) x 8 hidden-split CTAs
#define CL 8              // cluster size (hidden split)
#define HSTR 272          // h_sh row stride (floats); k skew +4 per 64 kills q-conflicts
#define REC_GRID 152      // 19 clusters: 16 real + 3 dummy

// ---------------- scratch (static device allocations; no cudaMalloc) -------
__device__ float g_xp_f[SS * BB * G4H];   // [t][b][4H]
__device__ float g_xp_b[SS * BB * G4H];
__device__ float g_h0[BB * SS * 512];     // [b][t][512]
__device__ float g_h1[BB * SS * 512];
__device__ float g_ctx[BB * SS * 512];

__device__ __forceinline__ uint32_t smem_u32(const void* p) {
    uint32_t a;
    asm("{ .reg .u64 t; cvta.to.shared.u64 t, %1; cvt.u32.u64 %0, t; }"
        : "=r"(a) : "l"(p));
    return a;
}

// packed f32x2 FMA: acc.{lo,hi} += w.{lo,hi} * h.{lo,hi}
#define FMA2(acc, w, h) \
    asm("fma.rn.f32x2 %0, %1, %2, %0;" : "+l"(acc) : "l"(w), "l"(h))

__device__ __forceinline__ float f2sum(unsigned long long v) {
    float lo, hi;
    asm("mov.b64 {%0,%1}, %2;" : "=f"(lo), "=f"(hi) : "l"(v));
    return lo + hi;
}

// ---------------- tf32 tensor-core GEMM (unchanged, proven) ----------------
#define BK 32
#define KSTRIDE 136

__device__ __forceinline__ void mma_tf32(float* c, const uint32_t* a, const uint32_t* b) {
    asm volatile(
        "mma.sync.aligned.m16n8k8.row.col.f32.tf32.tf32.f32 "
        "{%0,%1,%2,%3}, {%4,%5,%6,%7}, {%8,%9}, {%0,%1,%2,%3};"
        : "+f"(c[0]), "+f"(c[1]), "+f"(c[2]), "+f"(c[3])
        : "r"(a[0]), "r"(a[1]), "r"(a[2]), "r"(a[3]), "r"(b[0]), "r"(b[1]));
}

__global__ void __launch_bounds__(256, 2) gemm_kernel(
    const float* __restrict__ Aext, int asel,
    const float* __restrict__ W, const float* __restrict__ bias,
    float* __restrict__ outext, int osel,
    int N, int K, long sB, long sT, int mode)
{
    const float* A = (asel == 0) ? Aext : (asel == 1 ? g_h0 : g_ctx);
    float* out = (osel == 2) ? outext : (osel == 0 ? g_xp_f : g_xp_b);

    __shared__ float As[BK][KSTRIDE];
    __shared__ float Bs[BK][KSTRIDE];

    int tid  = threadIdx.x;
    int row0 = blockIdx.x * 128;
    int col0 = blockIdx.y * 128;

    int lr = tid & 127;
    int lh = (tid >> 7) * 16;

    long aoff;
    if (mode == 0) { int R = row0 + lr; aoff = (long)(R & 31) * sB + (long)(R >> 5) * sT; }
    else           { aoff = (long)(row0 + lr) * K; }
    const float* Ap = A + aoff + lh;
    const float* Wp = W + (long)(col0 + lr) * K + lh;

    int lane = tid & 31, warp = tid >> 5;
    int wm = warp >> 1, wn = warp & 1;
    int gid = lane >> 2, tid4 = lane & 3;

    float acc[2][8][4];
#pragma unroll
    for (int mi = 0; mi < 2; mi++)
#pragma unroll
        for (int ni = 0; ni < 8; ni++)
#pragma unroll
            for (int q = 0; q < 4; q++) acc[mi][ni][q] = 0.f;

    for (int k0 = 0; k0 < K; k0 += BK) {
#pragma unroll
        for (int c = 0; c < 4; c++) {
            float4 av = *(const float4*)(Ap + k0 + c * 4);
            float4 wv = *(const float4*)(Wp + k0 + c * 4);
            int kk = lh + c * 4;
            As[kk + 0][lr] = av.x; As[kk + 1][lr] = av.y;
            As[kk + 2][lr] = av.z; As[kk + 3][lr] = av.w;
            Bs[kk + 0][lr] = wv.x; Bs[kk + 1][lr] = wv.y;
            Bs[kk + 2][lr] = wv.z; Bs[kk + 3][lr] = wv.w;
        }
        __syncthreads();

#pragma unroll
        for (int kk = 0; kk < BK; kk += 8) {
            uint32_t af[2][4];
#pragma unroll
            for (int mi = 0; mi < 2; mi++) {
                int r0 = wm * 32 + mi * 16 + gid;
                af[mi][0] = __float_as_uint(As[kk + tid4][r0]);
                af[mi][1] = __float_as_uint(As[kk + tid4][r0 + 8]);
                af[mi][2] = __float_as_uint(As[kk + tid4 + 4][r0]);
                af[mi][3] = __float_as_uint(As[kk + tid4 + 4][r0 + 8]);
            }
            uint32_t bf[8][2];
#pragma unroll
            for (int ni = 0; ni < 8; ni++) {
                int n0 = wn * 64 + ni * 8 + gid;
                bf[ni][0] = __float_as_uint(Bs[kk + tid4][n0]);
                bf[ni][1] = __float_as_uint(Bs[kk + tid4 + 4][n0]);
            }
#pragma unroll
            for (int mi = 0; mi < 2; mi++)
#pragma unroll
                for (int ni = 0; ni < 8; ni++)
                    mma_tf32(acc[mi][ni], af[mi], bf[ni]);
        }
        __syncthreads();
    }

#pragma unroll
    for (int mi = 0; mi < 2; mi++) {
        int r = row0 + wm * 32 + mi * 16 + gid;
#pragma unroll
        for (int ni = 0; ni < 8; ni++) {
            int cc = col0 + wn * 64 + ni * 8 + tid4 * 2;
            float b0 = bias[cc], b1 = bias[cc + 1];
            float2 v0 = make_float2(acc[mi][ni][0] + b0, acc[mi][ni][1] + b1);
            float2 v1 = make_float2(acc[mi][ni][2] + b0, acc[mi][ni][3] + b1);
            *(float2*)(out + (long)r * N + cc)       = v0;
            *(float2*)(out + (long)(r + 8) * N + cc) = v1;
        }
    }
}

// ---------------- recurrence: weight-stationary registers -------------------
// 512 threads. Thread (r = tid>>2, q = tid&3): owns gate row r, k-quarter q
// (64 W values in regs). Computes partials for all 4 batches; shfl butterfly
// reduces over q AND transposes so lane q holds the full dot for batch q.
// Lane layout: lane = (r&7)*4 + q; warp = r>>3 (16 warps).
__global__ void __launch_bounds__(512, 1) __cluster_dims__(CL, 1, 1)
rec_kernel(const float* __restrict__ w_hh_f, const float* __restrict__ w_hh_b,
           int layer)
{
    if (blockIdx.x >= 16 * CL) return;   // dummy clusters (grid padding)

    __shared__ __align__(16) float h_sh[2 * 4 * HSTR];   // [buf][b][k skewed]
    __shared__ __align__(16) float g_sh[128 * 4];        // [row][b]

    int tid = threadIdx.x;
    unsigned crank;
    asm("mov.u32 %0, %%cluster_ctarank;" : "=r"(crank));
    int cidx = blockIdx.x / CL;
    int dir  = cidx >> 3;
    int bg   = cidx & 7;

    const float* Whh = dir ? w_hh_b : w_hh_f;
    const float* xp  = dir ? g_xp_b : g_xp_f;
    float* hout = layer ? g_h1 : g_h0;

    int r = tid >> 2, q = tid & 3;
    long grow = (long)(r >> 5) * HH + crank * 32 + (r & 31);

    // W into registers: 64 floats = 16 x ulonglong2 (f32x2 pairs)
    ulonglong2 wreg[16];
    {
        const ulonglong2* wp = (const ulonglong2*)(Whh + grow * HH + q * 64);
#pragma unroll
        for (int i = 0; i < 16; i++) wreg[i] = wp[i];
    }

    for (int i = tid; i < 2 * 4 * HSTR; i += 512) h_sh[i] = 0.f;

    // nonlin mapping (tid < 128): hidden njl = tid>>2, batch nb = tid&3
    int njl = tid >> 2, nb = tid & 3;
    float c = 0.f;

    // hoisted DSMEM peer addresses + skewed h offsets
    uint32_t h_u32 = smem_u32(h_sh);
    uint32_t rem[CL];
#pragma unroll
    for (int pr = 0; pr < CL; pr++)
        asm("mapa.shared::cluster.u32 %0, %1, %2;" : "=r"(rem[pr]) : "r"(h_u32), "r"(pr));
    int hk  = (int)crank * 32 + njl;
    int hkk = hk + 4 * (hk >> 6);                       // skew
    uint32_t offA = (uint32_t)(((0 * 4 + nb) * HSTR + hkk) * 4);
    uint32_t offB = (uint32_t)(((1 * 4 + nb) * HSTR + hkk) * 4);

    int p1 = q & 1, p2 = (q >> 1) & 1;
    long xrow = (long)(bg * 4 + q) * G4H + grow;         // xp element for (r, b=q)

    __syncthreads();
    asm volatile("barrier.cluster.arrive.aligned;" ::: "memory");
    asm volatile("barrier.cluster.wait.aligned;"   ::: "memory");

    // xp prefetch for t=0
    int tt0 = dir ? (SS - 1) : 0;
    float xv = xp[(long)tt0 * (BB * G4H) + xrow];

    for (int t = 0; t < SS; t++) {
        int tt = dir ? (SS - 1 - t) : t;
        int rbuf = t & 1, wbuf = rbuf ^ 1;

        // GEMV: 4 batch partials, W from regs, h broadcast from smem
        const ulonglong2* h0p = (const ulonglong2*)(h_sh + (rbuf * 4 + 0) * HSTR + q * 68);
        const ulonglong2* h1p = (const ulonglong2*)(h_sh + (rbuf * 4 + 1) * HSTR + q * 68);
        const ulonglong2* h2p = (const ulonglong2*)(h_sh + (rbuf * 4 + 2) * HSTR + q * 68);
        const ulonglong2* h3p = (const ulonglong2*)(h_sh + (rbuf * 4 + 3) * HSTR + q * 68);

        unsigned long long a0 = 0ull, a1 = 0ull, a2 = 0ull, a3 = 0ull;
#pragma unroll
        for (int i = 0; i < 16; i++) {
            ulonglong2 w2 = wreg[i];
            ulonglong2 h0 = h0p[i], h1 = h1p[i], h2 = h2p[i], h3 = h3p[i];
            FMA2(a0, w2.x, h0.x); FMA2(a1, w2.x, h1.x);
            FMA2(a2, w2.x, h2.x); FMA2(a3, w2.x, h3.x);
            FMA2(a0, w2.y, h0.y); FMA2(a1, w2.y, h1.y);
            FMA2(a2, w2.y, h2.y); FMA2(a3, w2.y, h3.y);
        }
        float v0 = f2sum(a0), v1 = f2sum(a1), v2 = f2sum(a2), v3 = f2sum(a3);

        // butterfly: reduce over q + transpose to batch q
        float s0 = p1 ? v0 : v1, k0 = p1 ? v1 : v0;
        float ua = k0 + __shfl_xor_sync(0xffffffffu, s0, 1);
        float s1 = p1 ? v2 : v3, k1 = p1 ? v3 : v2;
        float ub = k1 + __shfl_xor_sync(0xffffffffu, s1, 1);
        float s2 = p2 ? ua : ub, k2 = p2 ? ub : ua;
        float gv = k2 + __shfl_xor_sync(0xffffffffu, s2, 2);

        g_sh[r * 4 + q] = gv + xv;

        // prefetch xp for t+1 (flies through nonlin + barrier)
        if (t < SS - 1) {
            int tn = dir ? (SS - 2 - t) : (t + 1);
            xv = xp[(long)tn * (BB * G4H) + xrow];
        }
        __syncthreads();

        if (tid < 128) {
            float gi = g_sh[(0 * 32 + njl) * 4 + nb];
            float gf = g_sh[(1 * 32 + njl) * 4 + nb];
            float gg = g_sh[(2 * 32 + njl) * 4 + nb];
            float go = g_sh[(3 * 32 + njl) * 4 + nb];
            float si = 1.f / (1.f + __expf(-gi));
            float sf = 1.f / (1.f + __expf(-gf));
            float so = 1.f / (1.f + __expf(-go));
            float tg = tanhf(gg);
            c = sf * c + si * tg;
            float hval = so * tanhf(c);

            hout[((long)(bg * 4 + nb) * SS + tt) * 512 + dir * HH + crank * 32 + njl] = hval;

            if (t < SS - 1) {
                uint32_t off = wbuf ? offB : offA;
#pragma unroll
                for (int pr = 0; pr < CL; pr++)
                    asm volatile("st.shared::cluster.f32 [%0], %1;"
                                 :: "r"(rem[pr] + off), "f"(hval) : "memory");
            }
        }

        if (t < SS - 1) {
            asm volatile("barrier.cluster.arrive.aligned;" ::: "memory");
            asm volatile("barrier.cluster.wait.aligned;"   ::: "memory");
        }
    }
}

// ---------------- attention: causal softmax-weighted running average -------
__global__ void __launch_bounds__(512) attn_kernel(
    const float* __restrict__ attn_w, const float* __restrict__ attn_b)
{
    __shared__ float aw[512];
    __shared__ float e_sh[SS];
    __shared__ float red[16];

    int b = blockIdx.x, tid = threadIdx.x;
    int lane = tid & 31, warp = tid >> 5;
    const float* hb = g_h1 + (long)b * SS * 512;

    aw[tid] = attn_w[tid];
    float sb = attn_b[0];
    __syncthreads();

    for (int t = warp; t < SS; t += 16) {
        const float* hp = hb + (long)t * 512;
        float s = 0.f;
#pragma unroll
        for (int i = lane; i < 512; i += 32) s = fmaf(hp[i], aw[i], s);
#pragma unroll
        for (int o = 16; o; o >>= 1) s += __shfl_xor_sync(0xffffffffu, s, o);
        if (lane == 0) e_sh[t] = s + sb;
    }
    __syncthreads();

    float m = -3.4e38f;
    for (int t = tid; t < SS; t += 512) m = fmaxf(m, e_sh[t]);
#pragma unroll
    for (int o = 16; o; o >>= 1) m = fmaxf(m, __shfl_xor_sync(0xffffffffu, m, o));
    if (lane == 0) red[warp] = m;
    __syncthreads();
    m = red[0];
#pragma unroll
    for (int i = 1; i < 16; i++) m = fmaxf(m, red[i]);

    for (int t = tid; t < SS; t += 512) e_sh[t] = expf(e_sh[t] - m);
    __syncthreads();

    int d = tid;
    float num = 0.f, den = 0.f;
    const float* hd = hb + d;
    float* cd = g_ctx + (long)b * SS * 512 + d;
    for (int t = 0; t < SS; t++) {
        float ev = e_sh[t];
        den += ev;
        num = fmaf(ev, hd[(long)t * 512], num);
        cd[(long)t * 512] = num / den;
    }
}

// ---------------- launch ----------------------------------------------------
extern "C" void kernel_launch(void* const* d_in, const int* in_sizes, int n_in,
                              void* d_out, int out_size)
{
    const float* x       = (const float*)d_in[0];
    const float* wih0f   = (const float*)d_in[1];
    const float* whh0f   = (const float*)d_in[2];
    const float* b0f     = (const float*)d_in[3];
    const float* wih0b   = (const float*)d_in[4];
    const float* whh0b   = (const float*)d_in[5];
    const float* b0b     = (const float*)d_in[6];
    const float* wih1f   = (const float*)d_in[7];
    const float* whh1f   = (const float*)d_in[8];
    const float* b1f     = (const float*)d_in[9];
    const float* wih1b   = (const float*)d_in[10];
    const float* whh1b   = (const float*)d_in[11];
    const float* b1b     = (const float*)d_in[12];
    const float* attn_w  = (const float*)d_in[13];
    const float* attn_b  = (const float*)d_in[14];
    const float* head_w  = (const float*)d_in[15];
    const float* head_b  = (const float*)d_in[16];
    float* out = (float*)d_out;

    // ---- layer 0 ----
    gemm_kernel<<<dim3(MROWS / 128, G4H / 128), 256>>>(x, 0, wih0f, b0f, nullptr, 0,
                                                       G4H, DIN, (long)SS * DIN, DIN, 0);
    gemm_kernel<<<dim3(MROWS / 128, G4H / 128), 256>>>(x, 0, wih0b, b0b, nullptr, 1,
                                                       G4H, DIN, (long)SS * DIN, DIN, 0);
    rec_kernel<<<REC_GRID, 512>>>(whh0f, whh0b, 0);

    // ---- layer 1 ----
    gemm_kernel<<<dim3(MROWS / 128, G4H / 128), 256>>>(nullptr, 1, wih1f, b1f, nullptr, 0,
                                                       G4H, 512, (long)SS * 512, 512, 0);
    gemm_kernel<<<dim3(MROWS / 128, G4H / 128), 256>>>(nullptr, 1, wih1b, b1b, nullptr, 1,
                                                       G4H, 512, (long)SS * 512, 512, 0);
    rec_kernel<<<REC_GRID, 512>>>(whh1f, whh1b, 1);

    // ---- attention + head ----
    attn_kernel<<<BB, 512>>>(attn_w, attn_b);
    gemm_kernel<<<dim3(MROWS / 128, 1), 256>>>(nullptr, 2, head_w, head_b, out, 2,
                                               DIN, 512, 0, 0, 1);
}

// round 13
// speedup vs baseline: 1.8343x; 1.1554x over previous
#include <cuda_runtime.h>
#include <cuda_bf16.h>
#include <math.h>
#include <stdint.h>

// Problem constants
#define BB 32
#define SS 1024
#define DIN 128
#define HH 256
#define G4H 1024          // 4*H
#define MROWS 32768       // B*S

// Recurrence: 2 dirs x 8 batch-groups (clusters of 8) x 8 hidden-split CTAs
#define CL 8              // cluster size (hidden split)
#define HSTR 272          // h_sh row stride (floats); k skew +4 per 64
#define REC_GRID 152      // 19 clusters: 16 real + 3 dummy

// ---------------- scratch (static device allocations; no cudaMalloc) -------
__device__ float g_xp_f[SS * BB * G4H];   // [t][b][4H]
__device__ float g_xp_b[SS * BB * G4H];
__device__ float g_h0[BB * SS * 512];     // [b][t][512]
__device__ float g_h1[BB * SS * 512];
__device__ float g_ctx[BB * SS * 512];

__device__ __forceinline__ uint32_t smem_u32(const void* p) {
    uint32_t a;
    asm("{ .reg .u64 t; cvta.to.shared.u64 t, %1; cvt.u32.u64 %0, t; }"
        : "=r"(a) : "l"(p));
    return a;
}

#define FMA2(acc, w, h) \
    asm("fma.rn.f32x2 %0, %1, %2, %0;" : "+l"(acc) : "l"(w), "l"(h))

__device__ __forceinline__ float f2sum(unsigned long long v) {
    float lo, hi;
    asm("mov.b64 {%0,%1}, %2;" : "=f"(lo), "=f"(hi) : "l"(v));
    return lo + hi;
}

__device__ __forceinline__ float fast_sigmoid(float x) {
    return __fdividef(1.f, 1.f + __expf(-x));
}
__device__ __forceinline__ float fast_tanh(float x) {
    return __fdividef(2.f, 1.f + __expf(-2.f * x)) - 1.f;
}

// mbarrier helpers
#define MBAR_INIT(addr, cnt) \
    asm volatile("mbarrier.init.shared.b64 [%0], %1;" :: "r"(addr), "r"(cnt) : "memory")
#define MBAR_EXPECT_TX(addr, bytes) \
    asm volatile("mbarrier.arrive.expect_tx.shared.b64 _, [%0], %1;" \
                 :: "r"(addr), "r"(bytes) : "memory")
#define MBAR_WAIT(addr, par) do {                                            \
    uint32_t _done;                                                          \
    asm volatile("{\n\t.reg .pred p;\n\t"                                    \
        "mbarrier.try_wait.parity.acquire.cta.shared::cta.b64 p, [%1], %2;\n\t" \
        "selp.b32 %0, 1, 0, p;\n\t}"                                         \
        : "=r"(_done) : "r"(addr), "r"(par) : "memory");                     \
    while (!_done) {                                                         \
        asm volatile("{\n\t.reg .pred p;\n\t"                                \
            "mbarrier.try_wait.parity.acquire.cta.shared::cta.b64 p, [%1], %2, 0x989680;\n\t" \
            "selp.b32 %0, 1, 0, p;\n\t}"                                     \
            : "=r"(_done) : "r"(addr), "r"(par) : "memory");                 \
    }                                                                        \
} while (0)

// st.async with tx completion at remote mbarrier
#define ST_ASYNC_F32(remaddr, val, rembar) \
    asm volatile("st.async.shared::cluster.mbarrier::complete_tx::bytes.b32 [%0], %1, [%2];" \
                 :: "r"(remaddr), "r"(__float_as_uint(val)), "r"(rembar) : "memory")

// ---------------- tf32 tensor-core GEMM (unchanged, proven) ----------------
#define BK 32
#define KSTRIDE 136

__device__ __forceinline__ void mma_tf32(float* c, const uint32_t* a, const uint32_t* b) {
    asm volatile(
        "mma.sync.aligned.m16n8k8.row.col.f32.tf32.tf32.f32 "
        "{%0,%1,%2,%3}, {%4,%5,%6,%7}, {%8,%9}, {%0,%1,%2,%3};"
        : "+f"(c[0]), "+f"(c[1]), "+f"(c[2]), "+f"(c[3])
        : "r"(a[0]), "r"(a[1]), "r"(a[2]), "r"(a[3]), "r"(b[0]), "r"(b[1]));
}

__global__ void __launch_bounds__(256, 2) gemm_kernel(
    const float* __restrict__ Aext, int asel,
    const float* __restrict__ W, const float* __restrict__ bias,
    float* __restrict__ outext, int osel,
    int N, int K, long sB, long sT, int mode)
{
    const float* A = (asel == 0) ? Aext : (asel == 1 ? g_h0 : g_ctx);
    float* out = (osel == 2) ? outext : (osel == 0 ? g_xp_f : g_xp_b);

    __shared__ float As[BK][KSTRIDE];
    __shared__ float Bs[BK][KSTRIDE];

    int tid  = threadIdx.x;
    int row0 = blockIdx.x * 128;
    int col0 = blockIdx.y * 128;

    int lr = tid & 127;
    int lh = (tid >> 7) * 16;

    long aoff;
    if (mode == 0) { int R = row0 + lr; aoff = (long)(R & 31) * sB + (long)(R >> 5) * sT; }
    else           { aoff = (long)(row0 + lr) * K; }
    const float* Ap = A + aoff + lh;
    const float* Wp = W + (long)(col0 + lr) * K + lh;

    int lane = tid & 31, warp = tid >> 5;
    int wm = warp >> 1, wn = warp & 1;
    int gid = lane >> 2, tid4 = lane & 3;

    float acc[2][8][4];
#pragma unroll
    for (int mi = 0; mi < 2; mi++)
#pragma unroll
        for (int ni = 0; ni < 8; ni++)
#pragma unroll
            for (int q = 0; q < 4; q++) acc[mi][ni][q] = 0.f;

    for (int k0 = 0; k0 < K; k0 += BK) {
#pragma unroll
        for (int c = 0; c < 4; c++) {
            float4 av = *(const float4*)(Ap + k0 + c * 4);
            float4 wv = *(const float4*)(Wp + k0 + c * 4);
            int kk = lh + c * 4;
            As[kk + 0][lr] = av.x; As[kk + 1][lr] = av.y;
            As[kk + 2][lr] = av.z; As[kk + 3][lr] = av.w;
            Bs[kk + 0][lr] = wv.x; Bs[kk + 1][lr] = wv.y;
            Bs[kk + 2][lr] = wv.z; Bs[kk + 3][lr] = wv.w;
        }
        __syncthreads();

#pragma unroll
        for (int kk = 0; kk < BK; kk += 8) {
            uint32_t af[2][4];
#pragma unroll
            for (int mi = 0; mi < 2; mi++) {
                int r0 = wm * 32 + mi * 16 + gid;
                af[mi][0] = __float_as_uint(As[kk + tid4][r0]);
                af[mi][1] = __float_as_uint(As[kk + tid4][r0 + 8]);
                af[mi][2] = __float_as_uint(As[kk + tid4 + 4][r0]);
                af[mi][3] = __float_as_uint(As[kk + tid4 + 4][r0 + 8]);
            }
            uint32_t bf[8][2];
#pragma unroll
            for (int ni = 0; ni < 8; ni++) {
                int n0 = wn * 64 + ni * 8 + gid;
                bf[ni][0] = __float_as_uint(Bs[kk + tid4][n0]);
                bf[ni][1] = __float_as_uint(Bs[kk + tid4 + 4][n0]);
            }
#pragma unroll
            for (int mi = 0; mi < 2; mi++)
#pragma unroll
                for (int ni = 0; ni < 8; ni++)
                    mma_tf32(acc[mi][ni], af[mi], bf[ni]);
        }
        __syncthreads();
    }

#pragma unroll
    for (int mi = 0; mi < 2; mi++) {
        int r = row0 + wm * 32 + mi * 16 + gid;
#pragma unroll
        for (int ni = 0; ni < 8; ni++) {
            int cc = col0 + wn * 64 + ni * 8 + tid4 * 2;
            float b0 = bias[cc], b1 = bias[cc + 1];
            float2 v0 = make_float2(acc[mi][ni][0] + b0, acc[mi][ni][1] + b1);
            float2 v1 = make_float2(acc[mi][ni][2] + b0, acc[mi][ni][3] + b1);
            *(float2*)(out + (long)r * N + cc)       = v0;
            *(float2*)(out + (long)(r + 8) * N + cc) = v1;
        }
    }
}

// ---------------- noop: aligns rec_kernel to ncu's -s 5 capture slot --------
__global__ void noop_kernel() {}

// ---------------- recurrence: weight-stationary regs + st.async mbarrier ----
// 512 threads. Thread (r = tid>>2, q = tid&3): gate row r, k-quarter q in regs.
// Exchange: st.async f32 pushes carrying tx to peers' double-buffered mbarriers;
// consumers expect_tx(4096) + parity wait. No per-step cluster barrier.
__global__ void __launch_bounds__(512, 1) __cluster_dims__(CL, 1, 1)
rec_kernel(const float* __restrict__ w_hh_f, const float* __restrict__ w_hh_b,
           int layer)
{
    if (blockIdx.x >= 16 * CL) return;   // dummy clusters

    __shared__ __align__(16) float h_sh[2 * 4 * HSTR];   // [buf][b][k skewed]
    __shared__ __align__(16) float g_sh[128 * 4];        // [row][b]
    __shared__ __align__(8)  unsigned long long mbar[2];

    int tid = threadIdx.x;
    unsigned crank;
    asm("mov.u32 %0, %%cluster_ctarank;" : "=r"(crank));
    int cidx = blockIdx.x / CL;
    int dir  = cidx >> 3;
    int bg   = cidx & 7;

    const float* Whh = dir ? w_hh_b : w_hh_f;
    const float* xp  = dir ? g_xp_b : g_xp_f;
    float* hout = layer ? g_h1 : g_h0;

    int r = tid >> 2, q = tid & 3;
    long grow = (long)(r >> 5) * HH + crank * 32 + (r & 31);

    // W into registers: 64 floats = 16 x ulonglong2 (f32x2 pairs)
    ulonglong2 wreg[16];
    {
        const ulonglong2* wp = (const ulonglong2*)(Whh + grow * HH + q * 64);
#pragma unroll
        for (int i = 0; i < 16; i++) wreg[i] = wp[i];
    }

    for (int i = tid; i < 2 * 4 * HSTR; i += 512) h_sh[i] = 0.f;

    uint32_t mbar_u32 = smem_u32(mbar);
    if (tid == 0) {
        MBAR_INIT(mbar_u32 + 0, 1);
        MBAR_INIT(mbar_u32 + 8, 1);
    }

    // nonlin mapping (tid < 128): hidden njl = tid>>2, batch nb = tid&3
    int njl = tid >> 2, nb = tid & 3;
    float c = 0.f;

    // hoisted DSMEM peer addresses
    uint32_t h_u32 = smem_u32(h_sh);
    uint32_t rem_h[CL], rem_b[CL];
#pragma unroll
    for (int pr = 0; pr < CL; pr++) {
        asm("mapa.shared::cluster.u32 %0, %1, %2;" : "=r"(rem_h[pr]) : "r"(h_u32), "r"(pr));
        asm("mapa.shared::cluster.u32 %0, %1, %2;" : "=r"(rem_b[pr]) : "r"(mbar_u32), "r"(pr));
    }
    int hk  = (int)crank * 32 + njl;
    int hkk = hk + 4 * (hk >> 6);                        // skew
    uint32_t offA = (uint32_t)(((0 * 4 + nb) * HSTR + hkk) * 4);
    uint32_t offB = (uint32_t)(((1 * 4 + nb) * HSTR + hkk) * 4);

    int p1 = q & 1, p2 = (q >> 1) & 1;
    long xrow = (long)(bg * 4 + q) * G4H + grow;

    int par[2] = {0, 0};

    __syncthreads();
    asm volatile("barrier.cluster.arrive.aligned;" ::: "memory");   // mbarriers visible
    asm volatile("barrier.cluster.wait.aligned;"   ::: "memory");

    // xp prefetch for t=0
    int tt0 = dir ? (SS - 1) : 0;
    float xv = xp[(long)tt0 * (BB * G4H) + xrow];

    for (int t = 0; t < SS; t++) {
        int tt = dir ? (SS - 1 - t) : t;
        int rbuf = t & 1, wbuf = rbuf ^ 1;

        // wait for this step's h (pushed at end of t-1); t=0 uses local zeros
        if (t > 0) {
            MBAR_WAIT(mbar_u32 + 8 * rbuf, par[rbuf]);
            par[rbuf] ^= 1;
        }
        // post expectation for NEXT step's barrier (its previous phase consumed)
        if (t < SS - 1 && tid == 0)
            MBAR_EXPECT_TX(mbar_u32 + 8 * wbuf, 4096);

        // GEMV: 4 batch partials, W from regs, h broadcast from smem
        const ulonglong2* h0p = (const ulonglong2*)(h_sh + (rbuf * 4 + 0) * HSTR + q * 68);
        const ulonglong2* h1p = (const ulonglong2*)(h_sh + (rbuf * 4 + 1) * HSTR + q * 68);
        const ulonglong2* h2p = (const ulonglong2*)(h_sh + (rbuf * 4 + 2) * HSTR + q * 68);
        const ulonglong2* h3p = (const ulonglong2*)(h_sh + (rbuf * 4 + 3) * HSTR + q * 68);

        unsigned long long a0 = 0ull, a1 = 0ull, a2 = 0ull, a3 = 0ull;
#pragma unroll
        for (int i = 0; i < 16; i++) {
            ulonglong2 w2 = wreg[i];
            ulonglong2 h0 = h0p[i], h1 = h1p[i], h2 = h2p[i], h3 = h3p[i];
            FMA2(a0, w2.x, h0.x); FMA2(a1, w2.x, h1.x);
            FMA2(a2, w2.x, h2.x); FMA2(a3, w2.x, h3.x);
            FMA2(a0, w2.y, h0.y); FMA2(a1, w2.y, h1.y);
            FMA2(a2, w2.y, h2.y); FMA2(a3, w2.y, h3.y);
        }
        float v0 = f2sum(a0), v1 = f2sum(a1), v2 = f2sum(a2), v3 = f2sum(a3);

        // butterfly: reduce over q + transpose to batch q
        float s0 = p1 ? v0 : v1, k0 = p1 ? v1 : v0;
        float ua = k0 + __shfl_xor_sync(0xffffffffu, s0, 1);
        float s1 = p1 ? v2 : v3, k1 = p1 ? v3 : v2;
        float ub = k1 + __shfl_xor_sync(0xffffffffu, s1, 1);
        float s2 = p2 ? ua : ub, k2 = p2 ? ub : ua;
        float gv = k2 + __shfl_xor_sync(0xffffffffu, s2, 2);

        g_sh[r * 4 + q] = gv + xv;

        // prefetch xp for t+1
        if (t < SS - 1) {
            int tn = dir ? (SS - 2 - t) : (t + 1);
            xv = xp[(long)tn * (BB * G4H) + xrow];
        }
        __syncthreads();

        if (tid < 128) {
            float gi = g_sh[(0 * 32 + njl) * 4 + nb];
            float gf = g_sh[(1 * 32 + njl) * 4 + nb];
            float gg = g_sh[(2 * 32 + njl) * 4 + nb];
            float go = g_sh[(3 * 32 + njl) * 4 + nb];
            float si = fast_sigmoid(gi);
            float sf = fast_sigmoid(gf);
            float so = fast_sigmoid(go);
            float tg = fast_tanh(gg);
            c = sf * c + si * tg;
            float hval = so * fast_tanh(c);

            hout[((long)(bg * 4 + nb) * SS + tt) * 512 + dir * HH + crank * 32 + njl] = hval;

            if (t < SS - 1) {
                uint32_t off = wbuf ? offB : offA;
                uint32_t boff = 8u * (uint32_t)wbuf;
#pragma unroll
                for (int pr = 0; pr < CL; pr++)
                    ST_ASYNC_F32(rem_h[pr] + off, hval, rem_b[pr] + boff);
            }
        }
        // no per-step cluster barrier: mbarrier tx-completion carries ordering
    }
    // drain: ensure no CTA exits while peers still expect pushes (last step pushes none)
    asm volatile("barrier.cluster.arrive.aligned;" ::: "memory");
    asm volatile("barrier.cluster.wait.aligned;"   ::: "memory");
}

// ---------------- attention: causal softmax-weighted running average -------
__global__ void __launch_bounds__(512) attn_kernel(
    const float* __restrict__ attn_w, const float* __restrict__ attn_b)
{
    __shared__ float aw[512];
    __shared__ float e_sh[SS];
    __shared__ float red[16];

    int b = blockIdx.x, tid = threadIdx.x;
    int lane = tid & 31, warp = tid >> 5;
    const float* hb = g_h1 + (long)b * SS * 512;

    aw[tid] = attn_w[tid];
    float sb = attn_b[0];
    __syncthreads();

    for (int t = warp; t < SS; t += 16) {
        const float* hp = hb + (long)t * 512;
        float s = 0.f;
#pragma unroll
        for (int i = lane; i < 512; i += 32) s = fmaf(hp[i], aw[i], s);
#pragma unroll
        for (int o = 16; o; o >>= 1) s += __shfl_xor_sync(0xffffffffu, s, o);
        if (lane == 0) e_sh[t] = s + sb;
    }
    __syncthreads();

    float m = -3.4e38f;
    for (int t = tid; t < SS; t += 512) m = fmaxf(m, e_sh[t]);
#pragma unroll
    for (int o = 16; o; o >>= 1) m = fmaxf(m, __shfl_xor_sync(0xffffffffu, m, o));
    if (lane == 0) red[warp] = m;
    __syncthreads();
    m = red[0];
#pragma unroll
    for (int i = 1; i < 16; i++) m = fmaxf(m, red[i]);

    for (int t = tid; t < SS; t += 512) e_sh[t] = expf(e_sh[t] - m);
    __syncthreads();

    int d = tid;
    float num = 0.f, den = 0.f;
    const float* hd = hb + d;
    float* cd = g_ctx + (long)b * SS * 512 + d;
    for (int t = 0; t < SS; t++) {
        float ev = e_sh[t];
        den += ev;
        num = fmaf(ev, hd[(long)t * 512], num);
        cd[(long)t * 512] = num / den;
    }
}

// ---------------- launch ----------------------------------------------------
extern "C" void kernel_launch(void* const* d_in, const int* in_sizes, int n_in,
                              void* d_out, int out_size)
{
    const float* x       = (const float*)d_in[0];
    const float* wih0f   = (const float*)d_in[1];
    const float* whh0f   = (const float*)d_in[2];
    const float* b0f     = (const float*)d_in[3];
    const float* wih0b   = (const float*)d_in[4];
    const float* whh0b   = (const float*)d_in[5];
    const float* b0b     = (const float*)d_in[6];
    const float* wih1f   = (const float*)d_in[7];
    const float* whh1f   = (const float*)d_in[8];
    const float* b1f     = (const float*)d_in[9];
    const float* wih1b   = (const float*)d_in[10];
    const float* whh1b   = (const float*)d_in[11];
    const float* b1b     = (const float*)d_in[12];
    const float* attn_w  = (const float*)d_in[13];
    const float* attn_b  = (const float*)d_in[14];
    const float* head_w  = (const float*)d_in[15];
    const float* head_b  = (const float*)d_in[16];
    float* out = (float*)d_out;

    // ---- layer 0 ----
    gemm_kernel<<<dim3(MROWS / 128, G4H / 128), 256>>>(x, 0, wih0f, b0f, nullptr, 0,
                                                       G4H, DIN, (long)SS * DIN, DIN, 0);
    gemm_kernel<<<dim3(MROWS / 128, G4H / 128), 256>>>(x, 0, wih0b, b0b, nullptr, 1,
                                                       G4H, DIN, (long)SS * DIN, DIN, 0);
    noop_kernel<<<1, 32>>>();   // aligns rec_kernel to ncu -s 5 capture slot
    rec_kernel<<<REC_GRID, 512>>>(whh0f, whh0b, 0);

    // ---- layer 1 ----
    gemm_kernel<<<dim3(MROWS / 128, G4H / 128), 256>>>(nullptr, 1, wih1f, b1f, nullptr, 0,
                                                       G4H, 512, (long)SS * 512, 512, 0);
    gemm_kernel<<<dim3(MROWS / 128, G4H / 128), 256>>>(nullptr, 1, wih1b, b1b, nullptr, 1,
                                                       G4H, 512, (long)SS * 512, 512, 0);
    rec_kernel<<<REC_GRID, 512>>>(whh1f, whh1b, 1);

    // ---- attention + head ----
    attn_kernel<<<BB, 512>>>(attn_w, attn_b);
    gemm_kernel<<<dim3(MROWS / 128, 1), 256>>>(nullptr, 2, head_w, head_b, out, 2,
                                               DIN, 512, 0, 0, 1);
}